// round 2
// baseline (speedup 1.0000x reference)
#include <cuda_runtime.h>
#include <cstdint>

// Problem constants (fixed by the reference)
#define HH 1024
#define WW 1024
#define HWSZ (HH * WW)      // 1,048,576 cells
#define NF 64               // features
#define NP 100000           // pillars

// Scratch: per-cell winning pillar index (last-writer-wins == max pillar idx).
// __device__ global (no allocation allowed); re-initialized every launch so
// the captured graph is replay-deterministic.
__device__ int g_winner[HWSZ];

__global__ void init_winner_kernel() {
    int i = blockIdx.x * blockDim.x + threadIdx.x;
    if (i < HWSZ) g_winner[i] = -1;
}

// coords is int32 on device: JAX with x64 disabled materializes int64 requests
// as int32. Layout [NP, 3], x = col 2, y = col 1.
__global__ void scatter_winner_kernel(const int* __restrict__ coords) {
    int p = blockIdx.x * blockDim.x + threadIdx.x;
    if (p >= NP) return;
    int x = coords[3 * p + 2];
    int y = coords[3 * p + 1];
    if (x >= 0 && x < WW && y >= 0 && y < HH) {
        int cell = y * WW + x;
        // Sequential scatter semantics: later pillar index overwrites earlier.
        atomicMax(&g_winner[cell], p);
    }
}

__global__ void gather_out_kernel(const float* __restrict__ feat,
                                  float* __restrict__ out) {
    int c = blockIdx.x * blockDim.x + threadIdx.x;
    if (c >= HWSZ) return;
    int w = g_winner[c];
    if (w < 0) {
        // Empty cell: write zeros across all 64 feature planes.
        #pragma unroll
        for (int f = 0; f < NF; f++) {
            out[(size_t)f * HWSZ + c] = 0.0f;
        }
    } else {
        // Load the winner's full 256B feature row (contiguous, L2-resident),
        // scatter to 64 feature planes. Consecutive threads -> consecutive c,
        // so each plane store is a coalesced 128B warp transaction.
        const float4* row = (const float4*)(feat + (size_t)w * NF);
        #pragma unroll
        for (int i = 0; i < NF / 4; i++) {
            float4 v = __ldg(&row[i]);
            out[(size_t)(4 * i + 0) * HWSZ + c] = v.x;
            out[(size_t)(4 * i + 1) * HWSZ + c] = v.y;
            out[(size_t)(4 * i + 2) * HWSZ + c] = v.z;
            out[(size_t)(4 * i + 3) * HWSZ + c] = v.w;
        }
    }
}

extern "C" void kernel_launch(void* const* d_in, const int* in_sizes, int n_in,
                              void* d_out, int out_size) {
    const float* pillar_features = (const float*)d_in[0]; // [NP, 64] f32
    const int*   coords          = (const int*)d_in[1];   // [NP, 3] i32 (JAX x64-off)
    float*       out             = (float*)d_out;         // [1,64,1024,1024] f32

    {
        int threads = 256;
        int blocks = (HWSZ + threads - 1) / threads;
        init_winner_kernel<<<blocks, threads>>>();
    }
    {
        int threads = 256;
        int blocks = (NP + threads - 1) / threads;
        scatter_winner_kernel<<<blocks, threads>>>(coords);
    }
    {
        int threads = 256;
        int blocks = (HWSZ + threads - 1) / threads;
        gather_out_kernel<<<blocks, threads>>>(pillar_features, out);
    }
}

// round 3
// speedup vs baseline: 2.2466x; 2.2466x over previous
#include <cuda_runtime.h>
#include <cstdint>

// Problem constants (fixed by the reference)
#define HH 1024
#define WW 1024
#define HWSZ (HH * WW)      // 1,048,576 cells
#define NF 64               // features
#define NP 100000           // pillars

// Per-cell winner, encoded as (pillar_index + 1); 0 == empty.
// BSS zero-init makes the very first call correct with no init kernel;
// the gather kernel resets its words to 0 after consuming them, so every
// graph replay starts from the same (all-empty) state.
__device__ __align__(16) int g_winner[HWSZ];

// coords is int32 on device (JAX x64-off materializes int64 as int32).
// Layout [NP, 3]: x = col 2, y = col 1. Last-writer-wins == max pillar idx.
__global__ void scatter_winner_kernel(const int* __restrict__ coords) {
    int p = blockIdx.x * blockDim.x + threadIdx.x;
    if (p >= NP) return;
    int x = coords[3 * p + 2];
    int y = coords[3 * p + 1];
    if (x >= 0 && x < WW && y >= 0 && y < HH) {
        atomicMax(&g_winner[y * WW + x], p + 1);
    }
}

// Each thread owns 4 consecutive cells. For every 4-feature chunk:
// load float4 feature fragments for occupied cells (predicated, L2-resident),
// transpose in registers, store 4x STG.128 (4 cells x 1 feature each).
// Warps write 512B contiguous per plane -> fully coalesced.
__global__ void gather_out_kernel(const float* __restrict__ feat,
                                  float* __restrict__ out) {
    int g = blockIdx.x * blockDim.x + threadIdx.x;   // cell-group id
    if (g >= HWSZ / 4) return;
    int c0 = g * 4;

    int4 w4 = *reinterpret_cast<const int4*>(&g_winner[c0]);
    // Reset for the next graph replay (self-restoring state).
    *reinterpret_cast<int4*>(&g_winner[c0]) = make_int4(0, 0, 0, 0);

    int w[4] = {w4.x, w4.y, w4.z, w4.w};

    #pragma unroll
    for (int f4 = 0; f4 < NF / 4; f4++) {
        float4 v[4];
        #pragma unroll
        for (int j = 0; j < 4; j++) {
            if (w[j] > 0) {
                v[j] = __ldg(reinterpret_cast<const float4*>(
                    feat + (size_t)(w[j] - 1) * NF + f4 * 4));
            } else {
                v[j] = make_float4(0.f, 0.f, 0.f, 0.f);
            }
        }
        #pragma unroll
        for (int k = 0; k < 4; k++) {
            float4 o;
            o.x = reinterpret_cast<const float*>(&v[0])[k];
            o.y = reinterpret_cast<const float*>(&v[1])[k];
            o.z = reinterpret_cast<const float*>(&v[2])[k];
            o.w = reinterpret_cast<const float*>(&v[3])[k];
            *reinterpret_cast<float4*>(out + (size_t)(f4 * 4 + k) * HWSZ + c0) = o;
        }
    }
}

extern "C" void kernel_launch(void* const* d_in, const int* in_sizes, int n_in,
                              void* d_out, int out_size) {
    const float* pillar_features = (const float*)d_in[0]; // [NP, 64] f32
    const int*   coords          = (const int*)d_in[1];   // [NP, 3] i32
    float*       out             = (float*)d_out;         // [1,64,1024,1024] f32

    {
        int threads = 256;
        int blocks = (NP + threads - 1) / threads;
        scatter_winner_kernel<<<blocks, threads>>>(coords);
    }
    {
        int threads = 256;
        int groups = HWSZ / 4;
        int blocks = (groups + threads - 1) / threads;
        gather_out_kernel<<<blocks, threads>>>(pillar_features, out);
    }
}

// round 4
// speedup vs baseline: 2.5245x; 1.1237x over previous
#include <cuda_runtime.h>
#include <cstdint>

// Problem constants (fixed by the reference)
#define HH 1024
#define WW 1024
#define HWSZ (HH * WW)      // 1,048,576 cells
#define NF 64               // features
#define NP 100000           // pillars

// Per-cell winner, encoded as (pillar_index + 1); 0 == empty.
// BSS zero-init makes the very first call correct; clear_winner_kernel
// (launched after gather) restores the all-empty state for the next replay.
__device__ __align__(16) int g_winner[HWSZ];

// coords is int32 on device (JAX x64-off materializes int64 as int32).
// Layout [NP, 3]: x = col 2, y = col 1. Last-writer-wins == max pillar idx.
__global__ void scatter_winner_kernel(const int* __restrict__ coords) {
    int p = blockIdx.x * blockDim.x + threadIdx.x;
    if (p >= NP) return;
    int x = coords[3 * p + 2];
    int y = coords[3 * p + 1];
    if (x >= 0 && x < WW && y >= 0 && y < HH) {
        atomicMax(&g_winner[y * WW + x], p + 1);
    }
}

// One thread per (4-cell group, 4-feature chunk) tile.
// blockIdx.y = feature chunk (0..15); blockIdx.x covers cell groups.
// Winner array is re-read by all 16 chunk slices -> L2 hits (4MB resident).
// Output stores use evict-first (.cs) so the 256MB stream doesn't evict the
// L2-resident feature matrix.
__global__ __launch_bounds__(256) void gather_out_kernel(
        const float* __restrict__ feat,
        float* __restrict__ out) {
    int g = blockIdx.x * blockDim.x + threadIdx.x;   // cell-group id
    int f4 = blockIdx.y;                              // feature chunk
    int c0 = g * 4;

    int4 w4 = __ldg(reinterpret_cast<const int4*>(&g_winner[c0]));
    int w[4] = {w4.x, w4.y, w4.z, w4.w};

    float4 v[4];
    #pragma unroll
    for (int j = 0; j < 4; j++) {
        if (w[j] > 0) {
            v[j] = __ldg(reinterpret_cast<const float4*>(
                feat + (size_t)(w[j] - 1) * NF + f4 * 4));
        } else {
            v[j] = make_float4(0.f, 0.f, 0.f, 0.f);
        }
    }
    #pragma unroll
    for (int k = 0; k < 4; k++) {
        float4 o;
        o.x = reinterpret_cast<const float*>(&v[0])[k];
        o.y = reinterpret_cast<const float*>(&v[1])[k];
        o.z = reinterpret_cast<const float*>(&v[2])[k];
        o.w = reinterpret_cast<const float*>(&v[3])[k];
        __stcs(reinterpret_cast<float4*>(out + (size_t)(f4 * 4 + k) * HWSZ + c0), o);
    }
}

// Restore the all-empty winner state for the next graph replay.
__global__ void clear_winner_kernel() {
    int i = blockIdx.x * blockDim.x + threadIdx.x;
    if (i < HWSZ / 4) {
        reinterpret_cast<int4*>(g_winner)[i] = make_int4(0, 0, 0, 0);
    }
}

extern "C" void kernel_launch(void* const* d_in, const int* in_sizes, int n_in,
                              void* d_out, int out_size) {
    const float* pillar_features = (const float*)d_in[0]; // [NP, 64] f32
    const int*   coords          = (const int*)d_in[1];   // [NP, 3] i32
    float*       out             = (float*)d_out;         // [1,64,1024,1024] f32

    {
        int threads = 256;
        int blocks = (NP + threads - 1) / threads;
        scatter_winner_kernel<<<blocks, threads>>>(coords);
    }
    {
        int threads = 256;
        dim3 grid((HWSZ / 4 + threads - 1) / threads, NF / 4);
        gather_out_kernel<<<grid, threads>>>(pillar_features, out);
    }
    {
        int threads = 256;
        int blocks = (HWSZ / 4 + threads - 1) / threads;
        clear_winner_kernel<<<blocks, threads>>>();
    }
}